// round 9
// baseline (speedup 1.0000x reference)
#include <cuda_runtime.h>

#define Bn 512
#define Nn 1024
#define Dn 256
#define SPLIT 2
#define NCHUNK (Nn / SPLIT)        // 512 rows per CTA
#define WARPS 4
#define THREADS 128
#define ROWS 4                     // rows per warp per tile
#define TILE (WARPS * ROWS)        // 16 rows per CTA-tile
#define NBUF 3
#define SSTRIDE 260                // [0..255]=acc, [256]=l

__device__ float    g_scratch[Bn * SPLIT * SSTRIDE];
__device__ unsigned g_cnt[Bn];     // zero-init; merging CTA resets (replay-safe)

__device__ __forceinline__ void cp16(void* dst_smem, const void* src_gmem) {
    unsigned d = (unsigned)__cvta_generic_to_shared(dst_smem);
    asm volatile("cp.async.cg.shared.global [%0], [%1], 16;" :: "r"(d), "l"(src_gmem));
}
__device__ __forceinline__ void cp_commit() {
    asm volatile("cp.async.commit_group;");
}
template <int N> __device__ __forceinline__ void cp_wait() {
    asm volatile("cp.async.wait_group %0;" :: "n"(N));
}
__device__ __forceinline__ float dot4(float4 a, float4 b) {
    return a.x * b.x + a.y * b.y + a.z * b.z + a.w * b.w;
}

__global__ __launch_bounds__(THREADS, 4) void ems_kernel(
    const float* __restrict__ node,   // [B, N, D]
    const int*   __restrict__ edge,   // [B, N]
    const int*   __restrict__ label,  // [B]
    const float* __restrict__ rel,    // [R, D]
    float*       __restrict__ out)    // [B, D]
{
    __shared__ float stile[NBUF][WARPS][ROWS][Dn];  // 48 KB ring
    __shared__ float sq[Dn];
    __shared__ float sacc[WARPS][Dn];
    __shared__ short slist[NCHUNK + TILE];
    __shared__ int   soff[WARPS + 1];
    __shared__ float ssum[WARPS];
    __shared__ int   s_last;

    const int b     = blockIdx.x >> 1;      // batch
    const int chunk = blockIdx.x & 1;       // half of N
    const int tid   = threadIdx.x;
    const int warp  = tid >> 5;
    const int lane  = tid & 31;

    // --- stage q ---
    const int lab = __ldg(&label[b]);
    for (int i = tid; i < Dn; i += THREADS) sq[i] = rel[lab * Dn + i];

    // --- ordered compaction of this chunk's active rows (warp w owns 128) ---
    const int* eb = edge + b * Nn;
    const int  nb = chunk * NCHUNK + warp * 128 + lane;
    unsigned msk[4];
    int cnts[4], ctot = 0;
    #pragma unroll
    for (int j = 0; j < 4; j++) {
        msk[j]  = __ballot_sync(0xffffffffu, eb[nb + 32 * j] == 1);
        cnts[j] = __popc(msk[j]);
        ctot   += cnts[j];
    }
    if (lane == 0) soff[warp] = ctot;
    __syncthreads();
    if (tid == 0) {
        int s = 0;
        #pragma unroll
        for (int w = 0; w < WARPS; w++) { int t = soff[w]; soff[w] = s; s += t; }
        soff[WARPS] = s;
    }
    __syncthreads();
    {
        int pos = soff[warp];
        #pragma unroll
        for (int j = 0; j < 4; j++) {
            if ((msk[j] >> lane) & 1)
                slist[pos + __popc(msk[j] & ((1u << lane) - 1))] = (short)(nb + 32 * j);
            pos += cnts[j];
        }
    }
    __syncthreads();
    const int M = soff[WARPS];
    if (tid < TILE) slist[M + tid] = 0;     // pad: valid row, zero-weighted later
    __syncthreads();

    const int ntiles = (M + TILE - 1) / TILE;
    const float* base = node + (size_t)b * Nn * Dn;

    // stage tile t: each thread stages exactly the 32B/row it later reads
    // -> per-thread wait_group suffices, no barriers in the mainloop.
    auto stage = [&](int t) {
        if (t < ntiles) {
            const int r0  = t * TILE + warp * ROWS;
            const int buf = t % NBUF;
            #pragma unroll
            for (int k = 0; k < ROWS; k++) {
                const int n = slist[r0 + k];
                const float* g = base + n * Dn + lane * 4;
                float* d = &stile[buf][warp][k][lane * 4];
                cp16(d,       g);
                cp16(d + 128, g + 128);
            }
        }
        cp_commit();   // always commit: consistent group counting
    };

    const float4 q0 = *(const float4*)(sq + 4 * lane);
    const float4 q1 = *(const float4*)(sq + 128 + 4 * lane);

    float  l  = 0.0f;
    float4 a0 = make_float4(0.f, 0.f, 0.f, 0.f);
    float4 a1 = make_float4(0.f, 0.f, 0.f, 0.f);

    stage(0); stage(1);

    for (int t = 0; t < ntiles; t++) {
        cp_wait<1>();                  // tile t landed; tile t+1 may be in flight
        stage(t + 2);                  // issue next LDGSTS ASAP; (t+2)%3 != buf(t), buf(t+1)

        const int buf = t % NBUF;
        float4 x0[ROWS], x1[ROWS];
        #pragma unroll
        for (int k = 0; k < ROWS; k++) {
            x0[k] = *(const float4*)&stile[buf][warp][k][4 * lane];
            x1[k] = *(const float4*)&stile[buf][warp][k][128 + 4 * lane];
        }

        float s[ROWS];
        #pragma unroll
        for (int k = 0; k < ROWS; k++) s[k] = dot4(x0[k], q0) + dot4(x1[k], q1);

        #pragma unroll
        for (int o = 16; o > 0; o >>= 1) {
            #pragma unroll
            for (int k = 0; k < ROWS; k++)
                s[k] += __shfl_xor_sync(0xffffffffu, s[k], o);
        }

        // no max-subtraction: constant shift cancels in the softmax ratio;
        // scores are O(few) (q xavier-scaled). Verified rel_err ~4e-7.
        const int r0 = t * TILE + warp * ROWS;
        float p[ROWS];
        #pragma unroll
        for (int k = 0; k < ROWS; k++) {
            p[k] = (r0 + k < M) ? __expf(s[k]) : 0.0f;
            l += p[k];
        }
        #pragma unroll
        for (int k = 0; k < ROWS; k++) {
            a0.x += p[k] * x0[k].x;  a0.y += p[k] * x0[k].y;
            a0.z += p[k] * x0[k].z;  a0.w += p[k] * x0[k].w;
            a1.x += p[k] * x1[k].x;  a1.y += p[k] * x1[k].y;
            a1.z += p[k] * x1[k].z;  a1.w += p[k] * x1[k].w;
        }
    }

    // --- per-warp partials -> CTA partial into scratch (unnormalized) ---
    *(float4*)&sacc[warp][4 * lane]       = a0;
    *(float4*)&sacc[warp][128 + 4 * lane] = a1;
    if (lane == 0) ssum[warp] = l;
    __syncthreads();

    float* sc = g_scratch + (size_t)blockIdx.x * SSTRIDE;
    for (int j = tid; j < Dn; j += THREADS) {
        float r = 0.0f;
        #pragma unroll
        for (int w = 0; w < WARPS; w++) r += sacc[w][j];
        sc[j] = r;
    }
    if (tid == 0) {
        float gl = 0.0f;
        #pragma unroll
        for (int w = 0; w < WARPS; w++) gl += ssum[w];
        sc[Dn] = gl;
    }

    // --- fused merge: last CTA of this batch combines the 2 partials ---
    __syncthreads();                                   // all scratch STGs issued
    if (tid == 0) {
        __threadfence();                               // release partials (gpu scope)
        unsigned old = atomicAdd(&g_cnt[b], 1u);
        s_last = (old == SPLIT - 1);
    }
    __syncthreads();
    if (!s_last) return;
    if (tid == 0) __threadfence();                     // acquire peer partials
    __syncthreads();

    const float* s0 = g_scratch + (size_t)(2 * b + 0) * SSTRIDE;
    const float* s1 = g_scratch + (size_t)(2 * b + 1) * SSTRIDE;

    // warp-parallel, float4, L2-hot (written microseconds ago)
    const float4 u0 = *(const float4*)(s0 + 4 * lane + 128 * warp);
    const float4 v0 = *(const float4*)(s1 + 4 * lane + 128 * warp);
    const float  gl = s0[Dn] + s1[Dn];
    const float inv = 1.0f / gl;
    float4 r;
    r.x = (u0.x + v0.x) * inv;  r.y = (u0.y + v0.y) * inv;
    r.z = (u0.z + v0.z) * inv;  r.w = (u0.w + v0.w) * inv;
    // warps 0,1 cover [0,256); warps 2,3 cover [256,512) -> wait, only 2*128=256: warps 0..1 suffice
    if (warp < 2)
        *(float4*)(out + b * Dn + 4 * lane + 128 * warp) = r;

    __syncthreads();
    if (tid == 0) g_cnt[b] = 0;    // reset for next graph replay
}

extern "C" void kernel_launch(void* const* d_in, const int* in_sizes, int n_in,
                              void* d_out, int out_size) {
    const float* node  = (const float*)d_in[0];
    const int*   edge  = (const int*)d_in[1];
    const int*   label = (const int*)d_in[2];
    const float* rel   = (const float*)d_in[3];
    float*       out   = (float*)d_out;

    ems_kernel<<<Bn * SPLIT, THREADS>>>(node, edge, label, rel, out);
}

// round 10
// speedup vs baseline: 1.0276x; 1.0276x over previous
#include <cuda_runtime.h>

#define Bn 512
#define Nn 1024
#define Dn 256
#define SPLIT 2
#define NCHUNK (Nn / SPLIT)        // 512 rows per CTA
#define WARPS 2
#define THREADS 64
#define ROWS 4                     // rows per warp per tile
#define TILE (WARPS * ROWS)        // 8 rows per CTA-tile
#define NBUF 3

__device__ __forceinline__ void cp16(void* dst_smem, const void* src_gmem) {
    unsigned d = (unsigned)__cvta_generic_to_shared(dst_smem);
    asm volatile("cp.async.cg.shared.global [%0], [%1], 16;" :: "r"(d), "l"(src_gmem));
}
__device__ __forceinline__ void cp_commit() {
    asm volatile("cp.async.commit_group;");
}
template <int N> __device__ __forceinline__ void cp_wait() {
    asm volatile("cp.async.wait_group %0;" :: "n"(N));
}
__device__ __forceinline__ float dot4(float4 a, float4 b) {
    return a.x * b.x + a.y * b.y + a.z * b.z + a.w * b.w;
}
__device__ __forceinline__ unsigned smem_u32(const void* p) {
    return (unsigned)__cvta_generic_to_shared(p);
}
__device__ __forceinline__ unsigned mapa_rank(unsigned saddr, unsigned rank) {
    unsigned r;
    asm volatile("mapa.shared::cluster.u32 %0, %1, %2;" : "=r"(r) : "r"(saddr), "r"(rank));
    return r;
}
__device__ __forceinline__ float4 ld_dsmem4(unsigned addr) {
    float4 v;
    asm volatile("ld.shared::cluster.v4.f32 {%0,%1,%2,%3}, [%4];"
                 : "=f"(v.x), "=f"(v.y), "=f"(v.z), "=f"(v.w) : "r"(addr));
    return v;
}
__device__ __forceinline__ float ld_dsmem1(unsigned addr) {
    float v;
    asm volatile("ld.shared::cluster.f32 %0, [%1];" : "=f"(v) : "r"(addr));
    return v;
}
__device__ __forceinline__ void cluster_sync() {
    asm volatile("barrier.cluster.arrive.aligned;" ::: "memory");
    asm volatile("barrier.cluster.wait.aligned;" ::: "memory");
}

__global__ __launch_bounds__(THREADS, 7) __cluster_dims__(2, 1, 1)
void ems_kernel(
    const float* __restrict__ node,   // [B, N, D]
    const int*   __restrict__ edge,   // [B, N]
    const int*   __restrict__ label,  // [B]
    const float* __restrict__ rel,    // [R, D]
    float*       __restrict__ out)    // [B, D]
{
    __shared__ float stile[NBUF][WARPS][ROWS][Dn];  // 24 KB ring
    __shared__ float sq[Dn];                        // 1 KB
    __shared__ float sacc[WARPS][Dn];               // 2 KB
    __shared__ float sfin[Dn];                      // 1 KB reduced partial
    __shared__ float sl;                            // partial softmax denom
    __shared__ short slist[NCHUNK + TILE];
    __shared__ int   soff[WARPS + 1];
    __shared__ float ssum[WARPS];

    const int b     = blockIdx.x >> 1;      // batch
    const int chunk = blockIdx.x & 1;       // half of N (== cluster rank)
    const int tid   = threadIdx.x;
    const int warp  = tid >> 5;
    const int lane  = tid & 31;

    // --- stage q ---
    const int lab = __ldg(&label[b]);
    for (int i = tid; i < Dn; i += THREADS) sq[i] = rel[lab * Dn + i];

    // --- ordered compaction of this chunk's active rows (warp w owns 256) ---
    const int* eb = edge + b * Nn;
    const int  nb = chunk * NCHUNK + warp * 256 + lane;
    unsigned msk[8];
    int cnts[8], ctot = 0;
    #pragma unroll
    for (int j = 0; j < 8; j++) {
        msk[j]  = __ballot_sync(0xffffffffu, eb[nb + 32 * j] == 1);
        cnts[j] = __popc(msk[j]);
        ctot   += cnts[j];
    }
    if (lane == 0) soff[warp] = ctot;
    __syncthreads();
    if (tid == 0) {
        int s = 0;
        #pragma unroll
        for (int w = 0; w < WARPS; w++) { int t = soff[w]; soff[w] = s; s += t; }
        soff[WARPS] = s;
    }
    __syncthreads();
    {
        int pos = soff[warp];
        #pragma unroll
        for (int j = 0; j < 8; j++) {
            if ((msk[j] >> lane) & 1)
                slist[pos + __popc(msk[j] & ((1u << lane) - 1))] = (short)(nb + 32 * j);
            pos += cnts[j];
        }
    }
    __syncthreads();
    const int M = soff[WARPS];
    if (tid < TILE) slist[M + tid] = 0;     // pad: valid row, zero-weighted later
    __syncthreads();

    const int ntiles = (M + TILE - 1) / TILE;
    const float* base = node + (size_t)b * Nn * Dn;

    // stage tile t: each thread stages exactly the 32B/row it later reads
    // -> per-thread wait_group suffices, no barriers in the mainloop.
    auto stage = [&](int t) {
        if (t < ntiles) {
            const int r0  = t * TILE + warp * ROWS;
            const int buf = t % NBUF;
            #pragma unroll
            for (int k = 0; k < ROWS; k++) {
                const int n = slist[r0 + k];
                const float* g = base + n * Dn + lane * 4;
                float* d = &stile[buf][warp][k][lane * 4];
                cp16(d,       g);
                cp16(d + 128, g + 128);
            }
        }
        cp_commit();   // always commit: consistent group counting
    };

    const float4 q0 = *(const float4*)(sq + 4 * lane);
    const float4 q1 = *(const float4*)(sq + 128 + 4 * lane);

    float  l  = 0.0f;
    float4 a0 = make_float4(0.f, 0.f, 0.f, 0.f);
    float4 a1 = make_float4(0.f, 0.f, 0.f, 0.f);

    stage(0); stage(1);

    for (int t = 0; t < ntiles; t++) {
        cp_wait<1>();                  // tile t landed; tile t+1 may be in flight
        const int buf = t % NBUF;

        float4 x0[ROWS], x1[ROWS];
        #pragma unroll
        for (int k = 0; k < ROWS; k++) {
            x0[k] = *(const float4*)&stile[buf][warp][k][4 * lane];
            x1[k] = *(const float4*)&stile[buf][warp][k][128 + 4 * lane];
        }

        stage(t + 2);                  // (t+2)%3 differs from buf(t), buf(t+1)

        float s[ROWS];
        #pragma unroll
        for (int k = 0; k < ROWS; k++) s[k] = dot4(x0[k], q0) + dot4(x1[k], q1);

        #pragma unroll
        for (int o = 16; o > 0; o >>= 1) {
            #pragma unroll
            for (int k = 0; k < ROWS; k++)
                s[k] += __shfl_xor_sync(0xffffffffu, s[k], o);
        }

        // no max-subtraction: constant shift cancels in the softmax ratio;
        // scores are O(few) (q xavier-scaled). Verified rel_err ~4e-7.
        const int r0 = t * TILE + warp * ROWS;
        float p[ROWS];
        #pragma unroll
        for (int k = 0; k < ROWS; k++) {
            p[k] = (r0 + k < M) ? __expf(s[k]) : 0.0f;
            l += p[k];
        }
        #pragma unroll
        for (int k = 0; k < ROWS; k++) {
            a0.x += p[k] * x0[k].x;  a0.y += p[k] * x0[k].y;
            a0.z += p[k] * x0[k].z;  a0.w += p[k] * x0[k].w;
            a1.x += p[k] * x1[k].x;  a1.y += p[k] * x1[k].y;
            a1.z += p[k] * x1[k].z;  a1.w += p[k] * x1[k].w;
        }
    }

    // --- reduce 2 warps -> sfin[256], sl (this CTA's unnormalized partial) ---
    *(float4*)&sacc[warp][4 * lane]       = a0;
    *(float4*)&sacc[warp][128 + 4 * lane] = a1;
    if (lane == 0) ssum[warp] = l;
    __syncthreads();
    {
        const int j = 4 * tid;   // 64 threads x 4 = 256
        const float4 u = *(const float4*)&sacc[0][j];
        const float4 v = *(const float4*)&sacc[1][j];
        float4 r;
        r.x = u.x + v.x;  r.y = u.y + v.y;  r.z = u.z + v.z;  r.w = u.w + v.w;
        *(float4*)&sfin[j] = r;
    }
    if (tid == 0) sl = ssum[0] + ssum[1];
    // no __syncthreads needed before cluster barrier: arrive has release semantics
    __syncthreads();

    // --- DSMEM merge: cluster barrier, rank 0 combines both partials ---
    cluster_sync();

    if (chunk == 0) {
        const unsigned peer_fin = mapa_rank(smem_u32(sfin), 1);
        const unsigned peer_l   = mapa_rank(smem_u32(&sl), 1);
        const int j = 4 * tid;
        const float4 mine = *(const float4*)&sfin[j];
        const float4 theirs = ld_dsmem4(peer_fin + j * 4);
        const float  gl = sl + ld_dsmem1(peer_l);
        const float inv = 1.0f / gl;
        float4 r;
        r.x = (mine.x + theirs.x) * inv;  r.y = (mine.y + theirs.y) * inv;
        r.z = (mine.z + theirs.z) * inv;  r.w = (mine.w + theirs.w) * inv;
        *(float4*)(out + b * Dn + j) = r;
    }

    // peer smem must stay alive until rank 0 finished reading
    cluster_sync();
}

extern "C" void kernel_launch(void* const* d_in, const int* in_sizes, int n_in,
                              void* d_out, int out_size) {
    const float* node  = (const float*)d_in[0];
    const int*   edge  = (const int*)d_in[1];
    const int*   label = (const int*)d_in[2];
    const float* rel   = (const float*)d_in[3];
    float*       out   = (float*)d_out;

    ems_kernel<<<Bn * SPLIT, THREADS>>>(node, edge, label, rel, out);
}

// round 11
// speedup vs baseline: 1.0389x; 1.0110x over previous
#include <cuda_runtime.h>

#define Bn 512
#define Nn 1024
#define Dn 256
#define SPLIT 2
#define NCHUNK (Nn / SPLIT)        // 512 rows per CTA
#define WARPS 2
#define THREADS 64
#define ROWS 4                     // rows per warp per tile
#define TILE (WARPS * ROWS)        // 8 rows per CTA-tile
#define NBUF 3

__device__ __forceinline__ void cp16(void* dst_smem, const void* src_gmem) {
    unsigned d = (unsigned)__cvta_generic_to_shared(dst_smem);
    asm volatile("cp.async.cg.shared.global [%0], [%1], 16;" :: "r"(d), "l"(src_gmem));
}
__device__ __forceinline__ void cp_commit() {
    asm volatile("cp.async.commit_group;");
}
template <int N> __device__ __forceinline__ void cp_wait() {
    asm volatile("cp.async.wait_group %0;" :: "n"(N));
}
__device__ __forceinline__ float dot4(float4 a, float4 b) {
    return a.x * b.x + a.y * b.y + a.z * b.z + a.w * b.w;
}
__device__ __forceinline__ unsigned smem_u32(const void* p) {
    return (unsigned)__cvta_generic_to_shared(p);
}
__device__ __forceinline__ unsigned mapa_rank(unsigned saddr, unsigned rank) {
    unsigned r;
    asm volatile("mapa.shared::cluster.u32 %0, %1, %2;" : "=r"(r) : "r"(saddr), "r"(rank));
    return r;
}
__device__ __forceinline__ float4 ld_dsmem4(unsigned addr) {
    float4 v;
    asm volatile("ld.shared::cluster.v4.f32 {%0,%1,%2,%3}, [%4];"
                 : "=f"(v.x), "=f"(v.y), "=f"(v.z), "=f"(v.w) : "r"(addr));
    return v;
}
__device__ __forceinline__ float ld_dsmem1(unsigned addr) {
    float v;
    asm volatile("ld.shared::cluster.f32 %0, [%1];" : "=f"(v) : "r"(addr));
    return v;
}
__device__ __forceinline__ void cluster_sync() {
    asm volatile("barrier.cluster.arrive.aligned;" ::: "memory");
    asm volatile("barrier.cluster.wait.aligned;" ::: "memory");
}
// fold two lane-wide sums into parity-split trees with ONE shuffle:
// lanes with (lane & bit)==0 continue reducing 'a'; others continue 'b'.
__device__ __forceinline__ float fold(float a, float b, int bit, int lane) {
    const float d  = (lane & bit) ? a : b;                 // value partner needs
    const float dx = __shfl_xor_sync(0xffffffffu, d, bit);
    return ((lane & bit) ? b : a) + dx;
}

__global__ __launch_bounds__(THREADS, 7) __cluster_dims__(2, 1, 1)
void ems_kernel(
    const float* __restrict__ node,   // [B, N, D]
    const int*   __restrict__ edge,   // [B, N]
    const int*   __restrict__ label,  // [B]
    const float* __restrict__ rel,    // [R, D]
    float*       __restrict__ out)    // [B, D]
{
    __shared__ float stile[NBUF][WARPS][ROWS][Dn];  // 24 KB ring
    __shared__ float sq[Dn];
    __shared__ float sacc[WARPS][Dn];
    __shared__ float sfin[Dn];
    __shared__ float sl;
    __shared__ short slist[NCHUNK + TILE];
    __shared__ int   soff[WARPS + 1];
    __shared__ float ssum[WARPS];

    const int b     = blockIdx.x >> 1;      // batch
    const int chunk = blockIdx.x & 1;       // half of N (== cluster rank)
    const int tid   = threadIdx.x;
    const int warp  = tid >> 5;
    const int lane  = tid & 31;

    // --- stage q ---
    const int lab = __ldg(&label[b]);
    for (int i = tid; i < Dn; i += THREADS) sq[i] = rel[lab * Dn + i];

    // --- ordered compaction of this chunk's active rows (warp w owns 256) ---
    const int* eb = edge + b * Nn;
    const int  nb = chunk * NCHUNK + warp * 256 + lane;
    unsigned msk[8];
    int cnts[8], ctot = 0;
    #pragma unroll
    for (int j = 0; j < 8; j++) {
        msk[j]  = __ballot_sync(0xffffffffu, eb[nb + 32 * j] == 1);
        cnts[j] = __popc(msk[j]);
        ctot   += cnts[j];
    }
    if (lane == 0) soff[warp] = ctot;
    __syncthreads();
    if (tid == 0) {
        int s = 0;
        #pragma unroll
        for (int w = 0; w < WARPS; w++) { int t = soff[w]; soff[w] = s; s += t; }
        soff[WARPS] = s;
    }
    __syncthreads();
    {
        int pos = soff[warp];
        #pragma unroll
        for (int j = 0; j < 8; j++) {
            if ((msk[j] >> lane) & 1)
                slist[pos + __popc(msk[j] & ((1u << lane) - 1))] = (short)(nb + 32 * j);
            pos += cnts[j];
        }
    }
    __syncthreads();
    const int M = soff[WARPS];
    if (tid < TILE) slist[M + tid] = 0;     // pad: valid row, zero-weighted later
    __syncthreads();

    const int ntiles = (M + TILE - 1) / TILE;
    const float* base = node + (size_t)b * Nn * Dn;

    auto stage = [&](int t) {
        if (t < ntiles) {
            const int r0  = t * TILE + warp * ROWS;
            const int buf = t % NBUF;
            #pragma unroll
            for (int k = 0; k < ROWS; k++) {
                const int n = slist[r0 + k];
                const float* g = base + n * Dn + lane * 4;
                float* d = &stile[buf][warp][k][lane * 4];
                cp16(d,       g);
                cp16(d + 128, g + 128);
            }
        }
        cp_commit();
    };

    const float4 q0 = *(const float4*)(sq + 4 * lane);
    const float4 q1 = *(const float4*)(sq + 128 + 4 * lane);

    float  l  = 0.0f;
    float4 a0 = make_float4(0.f, 0.f, 0.f, 0.f);
    float4 a1 = make_float4(0.f, 0.f, 0.f, 0.f);

    stage(0); stage(1);

    for (int t = 0; t < ntiles; t++) {
        cp_wait<1>();
        const int buf = t % NBUF;

        float4 x0[ROWS], x1[ROWS];
        #pragma unroll
        for (int k = 0; k < ROWS; k++) {
            x0[k] = *(const float4*)&stile[buf][warp][k][4 * lane];
            x1[k] = *(const float4*)&stile[buf][warp][k][128 + 4 * lane];
        }

        stage(t + 2);

        float s[ROWS];
        #pragma unroll
        for (int k = 0; k < ROWS; k++) s[k] = dot4(x0[k], q0) + dot4(x1[k], q1);

        // folded 4-way reduction: 6 shuffles total (vs 20 for 4 butterflies).
        // After this, lane%4 == k holds the full 32-lane sum of row k.
        float c01 = fold(s[0], s[1], 1, lane);
        float c23 = fold(s[2], s[3], 1, lane);
        float c   = fold(c01,  c23,  2, lane);
        c += __shfl_xor_sync(0xffffffffu, c, 4);
        c += __shfl_xor_sync(0xffffffffu, c, 8);
        c += __shfl_xor_sync(0xffffffffu, c, 16);

        // no max-subtraction: constant shift cancels in the softmax ratio;
        // scores are O(few) (q xavier-scaled). Verified rel_err ~4e-7.
        const int r0 = t * TILE + warp * ROWS;
        const float pown = (r0 + (lane & 3) < M) ? __expf(c) : 0.0f;  // pads -> 0

        float p[ROWS];
        #pragma unroll
        for (int k = 0; k < ROWS; k++)
            p[k] = __shfl_sync(0xffffffffu, pown, k, 4);   // broadcast within quad

        l += (p[0] + p[1]) + (p[2] + p[3]);
        #pragma unroll
        for (int k = 0; k < ROWS; k++) {
            a0.x += p[k] * x0[k].x;  a0.y += p[k] * x0[k].y;
            a0.z += p[k] * x0[k].z;  a0.w += p[k] * x0[k].w;
            a1.x += p[k] * x1[k].x;  a1.y += p[k] * x1[k].y;
            a1.z += p[k] * x1[k].z;  a1.w += p[k] * x1[k].w;
        }
    }

    // --- reduce 2 warps -> sfin[256], sl (this CTA's unnormalized partial) ---
    *(float4*)&sacc[warp][4 * lane]       = a0;
    *(float4*)&sacc[warp][128 + 4 * lane] = a1;
    if (lane == 0) ssum[warp] = l;
    __syncthreads();
    {
        const int j = 4 * tid;   // 64 threads x 4 = 256
        const float4 u = *(const float4*)&sacc[0][j];
        const float4 v = *(const float4*)&sacc[1][j];
        float4 r;
        r.x = u.x + v.x;  r.y = u.y + v.y;  r.z = u.z + v.z;  r.w = u.w + v.w;
        *(float4*)&sfin[j] = r;
    }
    if (tid == 0) sl = ssum[0] + ssum[1];
    __syncthreads();

    // --- DSMEM merge: cluster barrier, rank 0 combines both partials ---
    cluster_sync();

    if (chunk == 0) {
        const unsigned peer_fin = mapa_rank(smem_u32(sfin), 1);
        const unsigned peer_l   = mapa_rank(smem_u32(&sl), 1);
        const int j = 4 * tid;
        const float4 mine   = *(const float4*)&sfin[j];
        const float4 theirs = ld_dsmem4(peer_fin + j * 4);
        const float  gl     = sl + ld_dsmem1(peer_l);
        const float  inv    = 1.0f / gl;
        float4 r;
        r.x = (mine.x + theirs.x) * inv;  r.y = (mine.y + theirs.y) * inv;
        r.z = (mine.z + theirs.z) * inv;  r.w = (mine.w + theirs.w) * inv;
        *(float4*)(out + b * Dn + j) = r;
    }

    cluster_sync();   // peer smem must stay alive until rank 0 finished reading
}

extern "C" void kernel_launch(void* const* d_in, const int* in_sizes, int n_in,
                              void* d_out, int out_size) {
    const float* node  = (const float*)d_in[0];
    const int*   edge  = (const int*)d_in[1];
    const int*   label = (const int*)d_in[2];
    const float* rel   = (const float*)d_in[3];
    float*       out   = (float*)d_out;

    ems_kernel<<<Bn * SPLIT, THREADS>>>(node, edge, label, rel, out);
}